// round 1
// baseline (speedup 1.0000x reference)
#include <cuda_runtime.h>

#define UNITS 10
#define T_IN  50
#define T_OUT 3

typedef unsigned long long u64;

// ---------- packed f32x2 helpers (sm_100a) ----------
__device__ __forceinline__ u64 pack2(float lo, float hi) {
    u64 r;
    asm("mov.b64 %0, {%1, %2};" : "=l"(r)
        : "r"(__float_as_uint(lo)), "r"(__float_as_uint(hi)));
    return r;
}
__device__ __forceinline__ float2 unpack2(u64 v) {
    unsigned lo, hi;
    asm("mov.b64 {%0, %1}, %2;" : "=r"(lo), "=r"(hi) : "l"(v));
    return make_float2(__uint_as_float(lo), __uint_as_float(hi));
}
__device__ __forceinline__ u64 fma2(u64 a, u64 b, u64 c) {
    u64 d;
    asm("fma.rn.f32x2 %0, %1, %2, %3;" : "=l"(d) : "l"(a), "l"(b), "l"(c));
    return d;
}
__device__ __forceinline__ u64 mul2(u64 a, u64 b) {
    u64 d;
    asm("mul.rn.f32x2 %0, %1, %2;" : "=l"(d) : "l"(a), "l"(b));
    return d;
}
__device__ __forceinline__ u64 relu2(u64 a) {
    float2 f = unpack2(a);
    return pack2(fmaxf(f.x, 0.0f), fmaxf(f.y, 0.0f));
}
// accurate fast sigmoid: 1/(1+2^(-x*log2e)); ex2/rcp approx ~1e-6 rel err
__device__ __forceinline__ float sigf(float x) {
    float e, r;
    asm("ex2.approx.f32 %0, %1;" : "=f"(e) : "f"(x * -1.4426950408889634f));
    asm("rcp.approx.f32 %0, %1;" : "=f"(r) : "f"(e + 1.0f));
    return r;
}
__device__ __forceinline__ u64 sig2(u64 a) {
    float2 f = unpack2(a);
    return pack2(sigf(f.x), sigf(f.y));
}
__device__ __forceinline__ u64 dupf(float w) {
    u64 b = (u64)__float_as_uint(w);
    return (b << 32) | b;
}

// dot over 10 packed weights (row must be 16B aligned)
__device__ __forceinline__ u64 dot10(const u64* __restrict__ row, const u64* h, u64 z) {
#pragma unroll
    for (int jj = 0; jj < 5; jj++) {
        ulonglong2 w = reinterpret_cast<const ulonglong2*>(row)[jj];
        z = fma2(h[2 * jj],     w.x, z);
        z = fma2(h[2 * jj + 1], w.y, z);
    }
    return z;
}
// dot over 20 packed weights
__device__ __forceinline__ u64 dot20(const u64* __restrict__ row, const u64* h, u64 z) {
#pragma unroll
    for (int jj = 0; jj < 10; jj++) {
        ulonglong2 w = reinterpret_cast<const ulonglong2*>(row)[jj];
        z = fma2(h[2 * jj],     w.x, z);
        z = fma2(h[2 * jj + 1], w.y, z);
    }
    return z;
}

__global__ __launch_bounds__(128)
void lstm_seq2seq_kernel(const float* __restrict__ inputs,
                         const float* __restrict__ W1,
                         const float* __restrict__ R1,
                         const float* __restrict__ b1,
                         const float* __restrict__ W2,
                         const float* __restrict__ R2,
                         const float* __restrict__ b2,
                         const float* __restrict__ Wd,
                         const float* __restrict__ bd,
                         float* __restrict__ out,
                         int B) {
    // Weights duplicated into both f32x2 halves, gate-major (transposed) rows.
    __shared__ __align__(16) u64 sR1[40][12];   // [gate][j]  (10 used, pad to 12)
    __shared__ __align__(16) u64 sM2[40][20];   // [gate][j]: j<10 -> W2, j>=10 -> R2
    __shared__ __align__(16) ulonglong2 sWB1[40]; // {dup(W1[g]), dup(b1[g])}
    __shared__ __align__(16) u64 sB2[40];
    __shared__ __align__(16) u64 sWd[10];

    const int tid = threadIdx.x;
    for (int idx = tid; idx < 400; idx += blockDim.x) {
        int j = idx / 40, g = idx % 40;
        sR1[g][j]      = dupf(R1[idx]);
        sM2[g][j]      = dupf(W2[idx]);
        sM2[g][10 + j] = dupf(R2[idx]);
    }
    for (int g = tid; g < 40; g += blockDim.x) {
        sWB1[g] = make_ulonglong2(dupf(W1[g]), dupf(b1[g]));
        sB2[g]  = dupf(b2[g]);
    }
    for (int u = tid; u < 10; u += blockDim.x) sWd[u] = dupf(Wd[u]);
    __syncthreads();

    const long long e0 = (long long)blockIdx.x * 2 * blockDim.x + 2 * tid;
    if (e0 >= B) return;
    const bool have2 = (e0 + 1 < B);
    const float* x0 = inputs + e0 * T_IN;
    const float* x1 = have2 ? (x0 + T_IN) : x0;

    // ---------------- LSTM1 ----------------
    u64 h[10], c[10];
#pragma unroll
    for (int u = 0; u < 10; u++) { h[u] = 0ull; c[u] = 0ull; }

#pragma unroll 1
    for (int t = 0; t < T_IN; t++) {
        const u64 x2 = pack2(x0[t], x1[t]);
        u64 hn[10];
#pragma unroll
        for (int u = 0; u < 10; u++) {
            const ulonglong2 wbI = sWB1[u];
            const ulonglong2 wbF = sWB1[10 + u];
            const ulonglong2 wbG = sWB1[20 + u];
            const ulonglong2 wbO = sWB1[30 + u];
            u64 zi = dot10(sR1[u],      h, fma2(x2, wbI.x, wbI.y));
            u64 zf = dot10(sR1[10 + u], h, fma2(x2, wbF.x, wbF.y));
            u64 zg = dot10(sR1[20 + u], h, fma2(x2, wbG.x, wbG.y));
            u64 zo = dot10(sR1[30 + u], h, fma2(x2, wbO.x, wbO.y));
            const u64 gi = sig2(zi);
            const u64 gf = sig2(zf);
            const u64 gg = relu2(zg);
            const u64 go = sig2(zo);
            c[u]  = fma2(gf, c[u], mul2(gi, gg));
            hn[u] = mul2(go, relu2(c[u]));
        }
#pragma unroll
        for (int u = 0; u < 10; u++) h[u] = hn[u];
    }

    // ---------------- LSTM2 (RepeatVector fused: input = h1 each step) ----
    u64 hh[20];  // [0..9] = h1 (constant), [10..19] = h2 state
#pragma unroll
    for (int u = 0; u < 10; u++) { hh[u] = h[u]; hh[10 + u] = 0ull; c[u] = 0ull; }

    const float bd0 = bd[0];
    const u64 bd2 = pack2(bd0, bd0);

#pragma unroll 1
    for (int s = 0; s < T_OUT; s++) {
        u64 hn[10];
#pragma unroll
        for (int u = 0; u < 10; u++) {
            u64 zi = dot20(sM2[u],      hh, sB2[u]);
            u64 zf = dot20(sM2[10 + u], hh, sB2[10 + u]);
            u64 zg = dot20(sM2[20 + u], hh, sB2[20 + u]);
            u64 zo = dot20(sM2[30 + u], hh, sB2[30 + u]);
            const u64 gi = sig2(zi);
            const u64 gf = sig2(zf);
            const u64 gg = relu2(zg);
            const u64 go = sig2(zo);
            c[u]  = fma2(gf, c[u], mul2(gi, gg));
            hn[u] = mul2(go, relu2(c[u]));
        }
        u64 acc = bd2;
#pragma unroll
        for (int u = 0; u < 10; u++) {
            hh[10 + u] = hn[u];
            acc = fma2(hn[u], sWd[u], acc);
        }
        const float2 o = unpack2(acc);
        out[e0 * T_OUT + s] = o.x;
        if (have2) out[(e0 + 1) * T_OUT + s] = o.y;
    }
}

extern "C" void kernel_launch(void* const* d_in, const int* in_sizes, int n_in,
                              void* d_out, int out_size) {
    const float* inputs = (const float*)d_in[0];
    const float* W1 = (const float*)d_in[1];
    const float* R1 = (const float*)d_in[2];
    const float* b1 = (const float*)d_in[3];
    const float* W2 = (const float*)d_in[4];
    const float* R2 = (const float*)d_in[5];
    const float* b2 = (const float*)d_in[6];
    const float* Wd = (const float*)d_in[7];
    const float* bd = (const float*)d_in[8];
    float* out = (float*)d_out;

    const int B = in_sizes[0] / T_IN;
    const int threads = 128;
    const int elems_per_block = threads * 2;
    const int blocks = (B + elems_per_block - 1) / elems_per_block;
    lstm_seq2seq_kernel<<<blocks, threads>>>(inputs, W1, R1, b1, W2, R2, b2,
                                             Wd, bd, out, B);
}

// round 2
// speedup vs baseline: 1.7927x; 1.7927x over previous
#include <cuda_runtime.h>

#define UNITS 10
#define T_IN  50
#define T_OUT 3
#define TPB   128
#define XPAD  129   // 128 elems + 1 pad -> conflict-free smem transpose

__device__ __forceinline__ float fast_sigmoid(float x) {
    // sigmoid(x) = 0.5*tanh(0.5x)+0.5 ; tanh.approx is a single MUFU op
    float t;
    asm("tanh.approx.f32 %0, %1;" : "=f"(t) : "f"(x * 0.5f));
    return fmaf(t, 0.5f, 0.5f);
}

// 10-long dot against gate-major weight row (12-float padded, 16B aligned)
__device__ __forceinline__ float dot10(const float* __restrict__ row,
                                       const float* __restrict__ h, float z) {
    const float4 w0 = *reinterpret_cast<const float4*>(row);
    const float4 w1 = *reinterpret_cast<const float4*>(row + 4);
    const float2 w2 = *reinterpret_cast<const float2*>(row + 8);
    z = fmaf(h[0], w0.x, z); z = fmaf(h[1], w0.y, z);
    z = fmaf(h[2], w0.z, z); z = fmaf(h[3], w0.w, z);
    z = fmaf(h[4], w1.x, z); z = fmaf(h[5], w1.y, z);
    z = fmaf(h[6], w1.z, z); z = fmaf(h[7], w1.w, z);
    z = fmaf(h[8], w2.x, z); z = fmaf(h[9], w2.y, z);
    return z;
}

// 20-long dot (row padded to 20, exact multiple of 4)
__device__ __forceinline__ float dot20(const float* __restrict__ row,
                                       const float* __restrict__ h, float z) {
#pragma unroll
    for (int q = 0; q < 5; q++) {
        const float4 w = *reinterpret_cast<const float4*>(row + 4 * q);
        z = fmaf(h[4 * q + 0], w.x, z);
        z = fmaf(h[4 * q + 1], w.y, z);
        z = fmaf(h[4 * q + 2], w.z, z);
        z = fmaf(h[4 * q + 3], w.w, z);
    }
    return z;
}

__global__ __launch_bounds__(TPB)
void lstm_seq2seq_kernel(const float* __restrict__ inputs,
                         const float* __restrict__ W1,
                         const float* __restrict__ R1,
                         const float* __restrict__ b1,
                         const float* __restrict__ W2,
                         const float* __restrict__ R2,
                         const float* __restrict__ b2,
                         const float* __restrict__ Wd,
                         const float* __restrict__ bd,
                         float* __restrict__ out) {
    __shared__ __align__(16) float sX[T_IN * XPAD];     // [t][elem] transposed inputs
    __shared__ __align__(16) float sR1[40][12];         // gate-major R1, zero-padded
    __shared__ __align__(16) float sM2[40][20];         // [gate][j]: j<10 W2, j>=10 R2
    __shared__ __align__(16) float2 sWB1[40];           // {W1[g], b1[g]}
    __shared__ __align__(16) float sB2[40];
    __shared__ __align__(16) float sWd[12];

    const int tid = threadIdx.x;

    // ---- stage weights (gate-major transpose) ----
    for (int idx = tid; idx < 480; idx += TPB) {        // 40 gates x 12 slots
        int g = idx / 12, j = idx % 12;
        sR1[g][j] = (j < 10) ? R1[j * 40 + g] : 0.0f;
    }
    for (int idx = tid; idx < 800; idx += TPB) {        // 40 gates x 20 slots
        int g = idx / 20, j = idx % 20;
        sM2[g][j] = (j < 10) ? W2[j * 40 + g] : R2[(j - 10) * 40 + g];
    }
    if (tid < 40) {
        sWB1[tid] = make_float2(W1[tid], b1[tid]);
        sB2[tid] = b2[tid];
    }
    if (tid < 12) sWd[tid] = (tid < 10) ? Wd[tid] : 0.0f;

    // ---- stage inputs, coalesced global -> transposed shared ----
    const long long blockBase = (long long)blockIdx.x * TPB;
    const float* gx = inputs + blockBase * T_IN;
#pragma unroll 1
    for (int idx = tid; idx < TPB * T_IN; idx += TPB) {
        int elem = idx / T_IN, t = idx % T_IN;
        sX[t * XPAD + elem] = gx[idx];
    }
    __syncthreads();

    // ---------------- LSTM1 ----------------
    float h[10], c[10];
#pragma unroll
    for (int u = 0; u < 10; u++) { h[u] = 0.0f; c[u] = 0.0f; }

#pragma unroll 1
    for (int t = 0; t < T_IN; t++) {
        const float x = sX[t * XPAD + tid];
        float hn[10];
#pragma unroll
        for (int u = 0; u < 10; u++) {
            const float2 wbI = sWB1[u];
            const float2 wbF = sWB1[10 + u];
            const float2 wbG = sWB1[20 + u];
            const float2 wbO = sWB1[30 + u];
            float zi = dot10(sR1[u],      h, fmaf(x, wbI.x, wbI.y));
            float zf = dot10(sR1[10 + u], h, fmaf(x, wbF.x, wbF.y));
            float zg = dot10(sR1[20 + u], h, fmaf(x, wbG.x, wbG.y));
            float zo = dot10(sR1[30 + u], h, fmaf(x, wbO.x, wbO.y));
            const float gi = fast_sigmoid(zi);
            const float gf = fast_sigmoid(zf);
            const float gg = fmaxf(zg, 0.0f);
            const float go = fast_sigmoid(zo);
            c[u] = fmaf(gf, c[u], gi * gg);
            hn[u] = go * fmaxf(c[u], 0.0f);
        }
#pragma unroll
        for (int u = 0; u < 10; u++) h[u] = hn[u];
    }

    // ---------------- LSTM2 (RepeatVector fused) ----------------
    float hh[20];   // [0..9] = h1 (constant input each step), [10..19] = h2
#pragma unroll
    for (int u = 0; u < 10; u++) { hh[u] = h[u]; hh[10 + u] = 0.0f; c[u] = 0.0f; }

    const float bd0 = bd[0];
    const long long e = blockBase + tid;

#pragma unroll 1
    for (int s = 0; s < T_OUT; s++) {
        float hn[10];
#pragma unroll
        for (int u = 0; u < 10; u++) {
            float zi = dot20(sM2[u],      hh, sB2[u]);
            float zf = dot20(sM2[10 + u], hh, sB2[10 + u]);
            float zg = dot20(sM2[20 + u], hh, sB2[20 + u]);
            float zo = dot20(sM2[30 + u], hh, sB2[30 + u]);
            const float gi = fast_sigmoid(zi);
            const float gf = fast_sigmoid(zf);
            const float gg = fmaxf(zg, 0.0f);
            const float go = fast_sigmoid(zo);
            c[u] = fmaf(gf, c[u], gi * gg);
            hn[u] = go * fmaxf(c[u], 0.0f);
        }
        float acc = bd0;
#pragma unroll
        for (int u = 0; u < 10; u++) {
            hh[10 + u] = hn[u];
            acc = fmaf(hn[u], sWd[u], acc);
        }
        out[e * T_OUT + s] = acc;
    }
}

extern "C" void kernel_launch(void* const* d_in, const int* in_sizes, int n_in,
                              void* d_out, int out_size) {
    const float* inputs = (const float*)d_in[0];
    const float* W1 = (const float*)d_in[1];
    const float* R1 = (const float*)d_in[2];
    const float* b1 = (const float*)d_in[3];
    const float* W2 = (const float*)d_in[4];
    const float* R2 = (const float*)d_in[5];
    const float* b2 = (const float*)d_in[6];
    const float* Wd = (const float*)d_in[7];
    const float* bd = (const float*)d_in[8];
    float* out = (float*)d_out;

    const int B = in_sizes[0] / T_IN;
    const int blocks = (B + TPB - 1) / TPB;
    lstm_seq2seq_kernel<<<blocks, TPB>>>(inputs, W1, R1, b1, W2, R2, b2,
                                         Wd, bd, out);
}